// round 10
// baseline (speedup 1.0000x reference)
#include <cuda_runtime.h>
#include <cuda_bf16.h>
#include <cstdint>

// Problem constants
#define N_MET   100000
#define N_RXN   50000
#define E_SUB   2000000
#define E_ALL   4000000
#define MSG_DIM 16
#define HIDDEN  32

// Persistent scratch
__device__ float g_hsum[N_RXN * HIDDEN];   // per-reaction sum of layer-1 h [50K][32]
__device__ float g_deg[N_RXN];             // per-reaction edge count (as float)
__device__ float g_Wc[HIDDEN * HIDDEN];    // W2m @ W1r  [32][32]
__device__ float g_bc[HIDDEN];             // b2m @ W1r  [32]

// ---------------------------------------------------------------------------
// helpers
// ---------------------------------------------------------------------------
__device__ __forceinline__ unsigned long long pack2(float a, float b) {
    unsigned long long r;
    asm("mov.b64 %0, {%1,%2};" : "=l"(r) : "f"(a), "f"(b));
    return r;
}
__device__ __forceinline__ unsigned long long fma2(unsigned long long a,
                                                   unsigned long long b,
                                                   unsigned long long c) {
    unsigned long long d;
    asm("fma.rn.f32x2 %0, %1, %2, %3;" : "=l"(d) : "l"(a), "l"(b), "l"(c));
    return d;
}
__device__ __forceinline__ float2 unpack2(unsigned long long a) {
    float2 f;
    asm("mov.b64 {%0,%1}, %2;" : "=f"(f.x), "=f"(f.y) : "l"(a));
    return f;
}
__device__ __forceinline__ float fast_ex2(float x) {
    float y; asm("ex2.approx.ftz.f32 %0, %1;" : "=f"(y) : "f"(x)); return y;
}
__device__ __forceinline__ float fast_rcp(float x) {
    float y; asm("rcp.approx.ftz.f32 %0, %1;" : "=f"(y) : "f"(x)); return y;
}
// single-MUFU tanh — edge kernel (validated: no precision impact at system level)
__device__ __forceinline__ float tanh_fast(float x) {
    float y; asm("tanh.approx.f32 %0, %1;" : "=f"(y) : "f"(x)); return y;
}
// accurate tanh via ex2+rcp (input pre-scaled by 2*log2(e)) — rate kernel
__device__ __forceinline__ float tanh_from_scaled(float u_scaled) {
    float e = fast_ex2(u_scaled);
    float r = fast_rcp(e + 1.0f);
    return fmaf(-2.0f, r, 1.0f);
}

__device__ __forceinline__ void red_add_v4(float* p, float a, float b, float c, float d) {
    asm volatile("red.global.add.v4.f32 [%0], {%1,%2,%3,%4};"
                 :: "l"(p), "f"(a), "f"(b), "f"(c), "f"(d) : "memory");
}
__device__ __forceinline__ void red_add_f32(float* p, float a) {
    asm volatile("red.global.add.f32 [%0], %1;" :: "l"(p), "f"(a) : "memory");
}

// ---------------------------------------------------------------------------
// Prep kernel: Wc = W2m[32,16] @ W1r[16,32],  bc = b2m[16] @ W1r[16,32]
// ---------------------------------------------------------------------------
__global__ void prep_kernel(const float* __restrict__ W2m,
                            const float* __restrict__ W1r,
                            const float* __restrict__ b2m) {
    int t = threadIdx.x;                 // 1024 threads
    int i = t >> 5, j = t & 31;
    float acc = 0.f;
    #pragma unroll
    for (int k = 0; k < MSG_DIM; k++)
        acc = fmaf(W2m[i * MSG_DIM + k], W1r[k * HIDDEN + j], acc);
    g_Wc[i * HIDDEN + j] = acc;
    if (t < HIDDEN) {
        float b = 0.f;
        #pragma unroll
        for (int k = 0; k < MSG_DIM; k++)
            b = fmaf(b2m[k], W1r[k * HIDDEN + t], b);
        g_bc[t] = b;
    }
}

// ---------------------------------------------------------------------------
// Kernel 1: per-edge layer-1 only:  h_j = tanh(x*W1[0,j] + s*W1[1,j] + b1[j])
// scatter-add h[32] into g_hsum[rxn] and 1.0 into g_deg[rxn].
// Layer 2 is algebraically folded into the rate kernel (linearity of segsum).
// ---------------------------------------------------------------------------
#define K1_TPB 128
#define K1_EPT 4

__global__ __launch_bounds__(K1_TPB)
void edge_h_kernel(const float* __restrict__ x_met,
                   const float* __restrict__ sto_sub,
                   const float* __restrict__ W1m,
                   const float* __restrict__ b1m,
                   const int*   __restrict__ met_sub,
                   const int*   __restrict__ rxn_sub) {
    // layer-1 weights pre-packed as u64 pairs (contiguous in memory already)
    __shared__ unsigned long long sWx[HIDDEN / 2];  // x-weights pairs
    __shared__ unsigned long long sWs[HIDDEN / 2];  // s-weights pairs
    __shared__ unsigned long long sBp[HIDDEN / 2];  // bias pairs

    const int t = threadIdx.x;
    if (t < 16)      sWx[t]      = reinterpret_cast<const unsigned long long*>(W1m)[t];
    else if (t < 32) sWs[t - 16] = reinterpret_cast<const unsigned long long*>(W1m)[t];
    else if (t < 48) sBp[t - 32] = reinterpret_cast<const unsigned long long*>(b1m)[t - 32];
    __syncthreads();

    const int tid4 = blockIdx.x * K1_TPB + t;      // quad index
    if (tid4 * K1_EPT >= E_SUB) return;            // E_SUB % 4 == 0

    int4   mi = __ldcs(reinterpret_cast<const int4*>(met_sub) + tid4);
    float4 sv = __ldcs(reinterpret_cast<const float4*>(sto_sub) + tid4);
    int4   ri = __ldcs(reinterpret_cast<const int4*>(rxn_sub) + tid4);

    float xv[K1_EPT];
    xv[0] = __ldg(x_met + mi.x); xv[1] = __ldg(x_met + mi.y);
    xv[2] = __ldg(x_met + mi.z); xv[3] = __ldg(x_met + mi.w);
    const float sc[K1_EPT] = {sv.x, sv.y, sv.z, sv.w};
    const int   rx[K1_EPT] = {ri.x, ri.y, ri.z, ri.w};

    unsigned long long xx[K1_EPT], ss[K1_EPT];
    float* base[K1_EPT];
    #pragma unroll
    for (int k = 0; k < K1_EPT; k++) {
        xx[k] = pack2(xv[k], xv[k]);
        ss[k] = pack2(sc[k], sc[k]);
        base[k] = g_hsum + (size_t)rx[k] * HIDDEN;
    }

    // 4 hidden dims per iteration; scatter immediately (nothing stays live)
    #pragma unroll
    for (int jp = 0; jp < HIDDEN / 4; jp++) {
        unsigned long long wx0 = sWx[2 * jp],     ws0 = sWs[2 * jp],     b0 = sBp[2 * jp];
        unsigned long long wx1 = sWx[2 * jp + 1], ws1 = sWs[2 * jp + 1], b1 = sBp[2 * jp + 1];
        #pragma unroll
        for (int k = 0; k < K1_EPT; k++) {
            unsigned long long u0 = fma2(xx[k], wx0, fma2(ss[k], ws0, b0));
            unsigned long long u1 = fma2(xx[k], wx1, fma2(ss[k], ws1, b1));
            float2 a = unpack2(u0), b = unpack2(u1);
            red_add_v4(base[k] + 4 * jp,
                       tanh_fast(a.x), tanh_fast(a.y),
                       tanh_fast(b.x), tanh_fast(b.y));
        }
    }

    #pragma unroll
    for (int k = 0; k < K1_EPT; k++)
        red_add_f32(g_deg + rx[k], 1.0f);
}

// ---------------------------------------------------------------------------
// Kernel 2: per-reaction rate MLP with folded layer-2:
//   a_j = hsum @ Wc[:,j] + deg*bc_j + b1r_j ;  v = softplus(tanh(a) @ W2r + b2r)
// ---------------------------------------------------------------------------
__global__ __launch_bounds__(256)
void rate_kernel(const float* __restrict__ b1r,
                 const float* __restrict__ W2r,
                 const float* __restrict__ b2r,
                 float* __restrict__ v_out) {
    __shared__ float sWc[HIDDEN * HIDDEN];   // 4 KB
    __shared__ float sbc[HIDDEN], sb1r[HIDDEN], sW2r[HIDDEN];
    __shared__ float sb2r;

    int t = threadIdx.x;
    for (int i = t; i < HIDDEN * HIDDEN; i += blockDim.x) sWc[i] = g_Wc[i];
    if (t < HIDDEN) { sbc[t] = g_bc[t]; sb1r[t] = b1r[t]; sW2r[t] = W2r[t]; }
    if (t == 0) sb2r = b2r[0];
    __syncthreads();

    int r = blockIdx.x * blockDim.x + t;
    if (r >= N_RXN) return;

    float hs[HIDDEN];
    const float4* hp = reinterpret_cast<const float4*>(g_hsum + (size_t)r * HIDDEN);
    #pragma unroll
    for (int q = 0; q < HIDDEN / 4; q++) {
        float4 hv = hp[q];
        hs[4 * q] = hv.x; hs[4 * q + 1] = hv.y; hs[4 * q + 2] = hv.z; hs[4 * q + 3] = hv.w;
    }
    float deg = g_deg[r];

    const float C = 2.8853900817779268f;  // 2*log2(e)
    float y = sb2r;
    #pragma unroll 4
    for (int j = 0; j < HIDDEN; j++) {
        float a = fmaf(deg, sbc[j], sb1r[j]);
        #pragma unroll
        for (int i = 0; i < HIDDEN; i++)
            a = fmaf(hs[i], sWc[i * HIDDEN + j], a);
        float z = tanh_from_scaled(a * C);
        y = fmaf(z, sW2r[j], y);
    }
    float sp = fmaxf(y, 0.f) + log1pf(expf(-fabsf(y)));
    v_out[r] = sp;
}

// ---------------------------------------------------------------------------
// Kernel 3: dxdt scatter — R1 winner shape (33.0 us measured)
// ---------------------------------------------------------------------------
__global__ __launch_bounds__(256)
void dxdt_kernel(const float* __restrict__ sto_all,
                 const int*   __restrict__ rxn_all,
                 const int*   __restrict__ met_all,
                 const float* __restrict__ v,
                 float* __restrict__ dxdt) {
    int i4 = blockIdx.x * blockDim.x + threadIdx.x;   // one thread = 4 edges
    if (i4 >= E_ALL / 4) return;
    float4 sv = reinterpret_cast<const float4*>(sto_all)[i4];
    int4   rv = reinterpret_cast<const int4*>(rxn_all)[i4];
    int4   mv = reinterpret_cast<const int4*>(met_all)[i4];
    red_add_f32(dxdt + mv.x, sv.x * __ldg(v + rv.x));
    red_add_f32(dxdt + mv.y, sv.y * __ldg(v + rv.y));
    red_add_f32(dxdt + mv.z, sv.z * __ldg(v + rv.z));
    red_add_f32(dxdt + mv.w, sv.w * __ldg(v + rv.w));
}

// ---------------------------------------------------------------------------
// Launch
// ---------------------------------------------------------------------------
extern "C" void kernel_launch(void* const* d_in, const int* in_sizes, int n_in,
                              void* d_out, int out_size) {
    const float* x_met   = (const float*)d_in[0];
    const float* sto_sub = (const float*)d_in[1];
    const float* sto_all = (const float*)d_in[2];
    const float* W1m     = (const float*)d_in[3];
    const float* b1m     = (const float*)d_in[4];
    const float* W2m     = (const float*)d_in[5];
    const float* b2m     = (const float*)d_in[6];
    const float* W1r     = (const float*)d_in[7];
    const float* b1r     = (const float*)d_in[8];
    const float* W2r     = (const float*)d_in[9];
    const float* b2r     = (const float*)d_in[10];
    const int*   met_sub = (const int*)d_in[11];
    const int*   rxn_sub = (const int*)d_in[12];
    const int*   met_all = (const int*)d_in[13];
    const int*   rxn_all = (const int*)d_in[14];

    float* dxdt = (float*)d_out;
    float* v    = (float*)d_out + N_MET;

    // zero scratch + dxdt
    void* p = nullptr;
    cudaGetSymbolAddress(&p, g_hsum);
    cudaMemsetAsync(p, 0, N_RXN * HIDDEN * sizeof(float));
    cudaGetSymbolAddress(&p, g_deg);
    cudaMemsetAsync(p, 0, N_RXN * sizeof(float));
    cudaMemsetAsync(dxdt, 0, N_MET * sizeof(float));

    prep_kernel<<<1, 1024>>>(W2m, W1r, b2m);

    int grid1 = (E_SUB / K1_EPT + K1_TPB - 1) / K1_TPB;
    edge_h_kernel<<<grid1, K1_TPB>>>(x_met, sto_sub, W1m, b1m, met_sub, rxn_sub);

    rate_kernel<<<(N_RXN + 255) / 256, 256>>>(b1r, W2r, b2r, v);

    dxdt_kernel<<<(E_ALL / 4 + 255) / 256, 256>>>(sto_all, rxn_all, met_all, v, dxdt);
}

// round 11
// speedup vs baseline: 1.9500x; 1.9500x over previous
#include <cuda_runtime.h>
#include <cuda_bf16.h>
#include <cstdint>

// Problem constants
#define N_MET   100000
#define N_RXN   50000
#define E_SUB   2000000
#define E_ALL   4000000
#define MSG_DIM 16
#define HIDDEN  32

// Persistent scratch: per-reaction accumulated messages [N_RXN][16]
__device__ float g_hrxn[N_RXN * MSG_DIM];

// Edge-MLP weights in constant memory.
// cW2q: W2m [32][16] row-major viewed as float4 -> LDC.128 (4 per j instead of
// 8 LDC.64: halves const-port issue time, which R6 showed at parity with FMA).
__constant__ float4 cW2q[HIDDEN * (MSG_DIM / 4)];
__constant__ float  cW1[2 * HIDDEN];   // row 0: x-weights, row 1: s-weights
__constant__ float  cB1[HIDDEN];
__constant__ float  cB2[MSG_DIM];

// ---------------------------------------------------------------------------
// helpers
// ---------------------------------------------------------------------------
__device__ __forceinline__ unsigned long long pack2(float a, float b) {
    unsigned long long r;
    asm("mov.b64 %0, {%1,%2};" : "=l"(r) : "f"(a), "f"(b));
    return r;
}
__device__ __forceinline__ unsigned long long fma2(unsigned long long a,
                                                   unsigned long long b,
                                                   unsigned long long c) {
    unsigned long long d;
    asm("fma.rn.f32x2 %0, %1, %2, %3;" : "=l"(d) : "l"(a), "l"(b), "l"(c));
    return d;
}
__device__ __forceinline__ float2 unpack2(unsigned long long a) {
    float2 f;
    asm("mov.b64 {%0,%1}, %2;" : "=f"(f.x), "=f"(f.y) : "l"(a));
    return f;
}
__device__ __forceinline__ float fast_ex2(float x) {
    float y; asm("ex2.approx.ftz.f32 %0, %1;" : "=f"(y) : "f"(x)); return y;
}
__device__ __forceinline__ float fast_rcp(float x) {
    float y; asm("rcp.approx.ftz.f32 %0, %1;" : "=f"(y) : "f"(x)); return y;
}
// single-MUFU tanh (MUFU.TANH) — edge kernel (measured: no precision impact)
__device__ __forceinline__ float tanh_fast(float x) {
    float y; asm("tanh.approx.f32 %0, %1;" : "=f"(y) : "f"(x)); return y;
}
// accurate tanh via ex2+rcp (input pre-scaled by 2*log2(e)) — rate kernel
__device__ __forceinline__ float tanh_from_scaled(float u_scaled) {
    float e = fast_ex2(u_scaled);
    float r = fast_rcp(e + 1.0f);
    return fmaf(-2.0f, r, 1.0f);
}

__device__ __forceinline__ void red_add_v4(float* p, float a, float b, float c, float d) {
    asm volatile("red.global.add.v4.f32 [%0], {%1,%2,%3,%4};"
                 :: "l"(p), "f"(a), "f"(b), "f"(c), "f"(d) : "memory");
}
__device__ __forceinline__ void red_add_f32(float* p, float a) {
    asm volatile("red.global.add.f32 [%0], %1;" :: "l"(p), "f"(a) : "memory");
}

// ---------------------------------------------------------------------------
// Kernel 1: per-edge message MLP + scatter-add into g_hrxn
//   msg = tanh([x,s] @ W1m + b1m) @ W2m + b2m      (2->32->16)
// R6 structure (measured best: 50.5us): 4 edges/thread, quad-amortized weight
// reads, accumulate 16 msg floats per edge, 4 REDG.v4 scatter per edge.
// Delta vs R6: W2 read as float4 (LDC.128) -> const-port time per j halves.
// ---------------------------------------------------------------------------
#define K1_TPB 128
#define K1_EPT 4

__global__ __launch_bounds__(K1_TPB)
void edge_msg_kernel(const float* __restrict__ x_met,
                     const float* __restrict__ sto_sub,
                     const int*   __restrict__ met_sub,
                     const int*   __restrict__ rxn_sub) {
    const int tid4 = blockIdx.x * K1_TPB + threadIdx.x;   // quad index
    if (tid4 * K1_EPT >= E_SUB) return;                   // E_SUB % 4 == 0

    // 3 vector stream loads (LDG.128) + 4 gathers, front-batched
    int4   mi = __ldcs(reinterpret_cast<const int4*>(met_sub) + tid4);
    float4 sv = __ldcs(reinterpret_cast<const float4*>(sto_sub) + tid4);
    int4   ri = __ldcs(reinterpret_cast<const int4*>(rxn_sub) + tid4);

    float x[K1_EPT], s[K1_EPT];
    x[0] = __ldg(x_met + mi.x); x[1] = __ldg(x_met + mi.y);
    x[2] = __ldg(x_met + mi.z); x[3] = __ldg(x_met + mi.w);
    s[0] = sv.x; s[1] = sv.y; s[2] = sv.z; s[3] = sv.w;

    // accumulators init = b2m   (4 edges x 8 u64)
    unsigned long long acc[K1_EPT][MSG_DIM / 2];
    #pragma unroll
    for (int q = 0; q < MSG_DIM / 2; q++) {
        unsigned long long b = pack2(cB2[2 * q], cB2[2 * q + 1]);
        #pragma unroll
        for (int k = 0; k < K1_EPT; k++) acc[k][q] = b;
    }

    #pragma unroll 2
    for (int j = 0; j < HIDDEN; j++) {
        const float wa = cW1[j], wb = cW1[HIDDEN + j], bj = cB1[j];
        float h[K1_EPT];
        #pragma unroll
        for (int k = 0; k < K1_EPT; k++) {
            float u = fmaf(x[k], wa, fmaf(s[k], wb, bj));
            h[k] = tanh_fast(u);
        }
        // W2 row j: 4 LDC.128, repack to 8 u64 (register-pair aliasing / alu movs)
        unsigned long long w2p[MSG_DIM / 2];
        #pragma unroll
        for (int q = 0; q < MSG_DIM / 4; q++) {
            float4 w = cW2q[j * (MSG_DIM / 4) + q];
            w2p[2 * q]     = pack2(w.x, w.y);
            w2p[2 * q + 1] = pack2(w.z, w.w);
        }
        #pragma unroll
        for (int k = 0; k < K1_EPT; k++) {
            unsigned long long hh = pack2(h[k], h[k]);
            #pragma unroll
            for (int q = 0; q < MSG_DIM / 2; q++)
                acc[k][q] = fma2(hh, w2p[q], acc[k][q]);
        }
    }

    const int rx[K1_EPT] = {ri.x, ri.y, ri.z, ri.w};
    #pragma unroll
    for (int k = 0; k < K1_EPT; k++) {
        float* p = g_hrxn + (size_t)rx[k] * MSG_DIM;
        #pragma unroll
        for (int q = 0; q < 4; q++) {
            float2 a = unpack2(acc[k][2 * q]);
            float2 b = unpack2(acc[k][2 * q + 1]);
            red_add_v4(p + 4 * q, a.x, a.y, b.x, b.y);
        }
    }
}

// ---------------------------------------------------------------------------
// Kernel 2: per-reaction rate MLP (exact tanh for precision headroom)
// ---------------------------------------------------------------------------
__global__ __launch_bounds__(256)
void rate_kernel(const float* __restrict__ W1r,
                 const float* __restrict__ b1r,
                 const float* __restrict__ W2r,
                 const float* __restrict__ b2r,
                 float* __restrict__ v_out) {
    __shared__ float sW1r[MSG_DIM * HIDDEN];
    __shared__ float sb1r[HIDDEN];
    __shared__ float sW2r[HIDDEN];
    __shared__ float sb2r;

    int t = threadIdx.x;
    for (int i = t; i < MSG_DIM * HIDDEN; i += blockDim.x) sW1r[i] = W1r[i];
    if (t < HIDDEN) { sb1r[t] = b1r[t]; sW2r[t] = W2r[t]; }
    if (t == 0) sb2r = b2r[0];
    __syncthreads();

    int r = blockIdx.x * blockDim.x + t;
    if (r >= N_RXN) return;

    float h[MSG_DIM];
    const float4* hp = reinterpret_cast<const float4*>(g_hrxn + (size_t)r * MSG_DIM);
    #pragma unroll
    for (int q = 0; q < 4; q++) {
        float4 hv = hp[q];
        h[4 * q] = hv.x; h[4 * q + 1] = hv.y; h[4 * q + 2] = hv.z; h[4 * q + 3] = hv.w;
    }

    const float C = 2.8853900817779268f;  // 2*log2(e)
    float y = sb2r;
    #pragma unroll 8
    for (int j = 0; j < HIDDEN; j++) {
        float a = sb1r[j];
        #pragma unroll
        for (int k = 0; k < MSG_DIM; k++) a = fmaf(h[k], sW1r[k * HIDDEN + j], a);
        float z = tanh_from_scaled(a * C);
        y = fmaf(z, sW2r[j], y);
    }
    float sp = fmaxf(y, 0.f) + log1pf(expf(-fabsf(y)));
    v_out[r] = sp;
}

// ---------------------------------------------------------------------------
// Kernel 3: dxdt scatter — R1/R6 winner shape
// ---------------------------------------------------------------------------
__global__ __launch_bounds__(256)
void dxdt_kernel(const float* __restrict__ sto_all,
                 const int*   __restrict__ rxn_all,
                 const int*   __restrict__ met_all,
                 const float* __restrict__ v,
                 float* __restrict__ dxdt) {
    int i4 = blockIdx.x * blockDim.x + threadIdx.x;   // one thread = 4 edges
    if (i4 >= E_ALL / 4) return;
    float4 sv = reinterpret_cast<const float4*>(sto_all)[i4];
    int4   rv = reinterpret_cast<const int4*>(rxn_all)[i4];
    int4   mv = reinterpret_cast<const int4*>(met_all)[i4];
    red_add_f32(dxdt + mv.x, sv.x * __ldg(v + rv.x));
    red_add_f32(dxdt + mv.y, sv.y * __ldg(v + rv.y));
    red_add_f32(dxdt + mv.z, sv.z * __ldg(v + rv.z));
    red_add_f32(dxdt + mv.w, sv.w * __ldg(v + rv.w));
}

// ---------------------------------------------------------------------------
// Launch
// ---------------------------------------------------------------------------
extern "C" void kernel_launch(void* const* d_in, const int* in_sizes, int n_in,
                              void* d_out, int out_size) {
    const float* x_met   = (const float*)d_in[0];
    const float* sto_sub = (const float*)d_in[1];
    const float* sto_all = (const float*)d_in[2];
    const float* W1m     = (const float*)d_in[3];
    const float* b1m     = (const float*)d_in[4];
    const float* W2m     = (const float*)d_in[5];
    const float* b2m     = (const float*)d_in[6];
    const float* W1r     = (const float*)d_in[7];
    const float* b1r     = (const float*)d_in[8];
    const float* W2r     = (const float*)d_in[9];
    const float* b2r     = (const float*)d_in[10];
    const int*   met_sub = (const int*)d_in[11];
    const int*   rxn_sub = (const int*)d_in[12];
    const int*   met_all = (const int*)d_in[13];
    const int*   rxn_all = (const int*)d_in[14];

    float* dxdt = (float*)d_out;
    float* v    = (float*)d_out + N_MET;

    // fill constant-memory weights (device-to-device async copies: capturable)
    cudaMemcpyToSymbolAsync(cW2q, W2m, HIDDEN * MSG_DIM * sizeof(float), 0,
                            cudaMemcpyDeviceToDevice);
    cudaMemcpyToSymbolAsync(cW1,  W1m, 2 * HIDDEN * sizeof(float), 0,
                            cudaMemcpyDeviceToDevice);
    cudaMemcpyToSymbolAsync(cB1,  b1m, HIDDEN * sizeof(float), 0,
                            cudaMemcpyDeviceToDevice);
    cudaMemcpyToSymbolAsync(cB2,  b2m, MSG_DIM * sizeof(float), 0,
                            cudaMemcpyDeviceToDevice);

    // zero scratch + dxdt
    void* hrxn_ptr = nullptr;
    cudaGetSymbolAddress(&hrxn_ptr, g_hrxn);
    cudaMemsetAsync(hrxn_ptr, 0, N_RXN * MSG_DIM * sizeof(float));
    cudaMemsetAsync(dxdt, 0, N_MET * sizeof(float));

    int grid1 = (E_SUB / K1_EPT + K1_TPB - 1) / K1_TPB;
    edge_msg_kernel<<<grid1, K1_TPB>>>(x_met, sto_sub, met_sub, rxn_sub);

    rate_kernel<<<(N_RXN + 255) / 256, 256>>>(W1r, b1r, W2r, b2r, v);

    dxdt_kernel<<<(E_ALL / 4 + 255) / 256, 256>>>(sto_all, rxn_all, met_all, v, dxdt);
}

// round 12
// speedup vs baseline: 2.0082x; 1.0299x over previous
#include <cuda_runtime.h>
#include <cuda_bf16.h>
#include <cstdint>

// Problem constants
#define N_MET   100000
#define N_RXN   50000
#define E_SUB   2000000
#define E_ALL   4000000
#define MSG_DIM 16
#define HIDDEN  32

// Persistent scratch: per-reaction accumulated messages [N_RXN][16]
__device__ float g_hrxn[N_RXN * MSG_DIM];

// Edge-MLP weights in constant memory (filled by async D2D copies each launch).
// cW2p: W2m [32][16] row-major reinterpreted as 8 packed f32-pairs per row.
// (R6 configuration — measured best at 50.5us.)
__constant__ unsigned long long cW2p[HIDDEN * (MSG_DIM / 2)];
__constant__ float cW1[2 * HIDDEN];   // row 0: x-weights, row 1: s-weights
__constant__ float cB1[HIDDEN];
__constant__ float cB2[MSG_DIM];

// ---------------------------------------------------------------------------
// helpers
// ---------------------------------------------------------------------------
__device__ __forceinline__ unsigned long long pack2(float a, float b) {
    unsigned long long r;
    asm("mov.b64 %0, {%1,%2};" : "=l"(r) : "f"(a), "f"(b));
    return r;
}
__device__ __forceinline__ unsigned long long fma2(unsigned long long a,
                                                   unsigned long long b,
                                                   unsigned long long c) {
    unsigned long long d;
    asm("fma.rn.f32x2 %0, %1, %2, %3;" : "=l"(d) : "l"(a), "l"(b), "l"(c));
    return d;
}
__device__ __forceinline__ float2 unpack2(unsigned long long a) {
    float2 f;
    asm("mov.b64 {%0,%1}, %2;" : "=f"(f.x), "=f"(f.y) : "l"(a));
    return f;
}
__device__ __forceinline__ float fast_ex2(float x) {
    float y; asm("ex2.approx.ftz.f32 %0, %1;" : "=f"(y) : "f"(x)); return y;
}
__device__ __forceinline__ float fast_rcp(float x) {
    float y; asm("rcp.approx.ftz.f32 %0, %1;" : "=f"(y) : "f"(x)); return y;
}
// single-MUFU tanh (MUFU.TANH) — edge kernel (measured: no precision impact)
__device__ __forceinline__ float tanh_fast(float x) {
    float y; asm("tanh.approx.f32 %0, %1;" : "=f"(y) : "f"(x)); return y;
}
// accurate tanh via ex2+rcp (input pre-scaled by 2*log2(e)) — rate kernel
__device__ __forceinline__ float tanh_from_scaled(float u_scaled) {
    float e = fast_ex2(u_scaled);
    float r = fast_rcp(e + 1.0f);
    return fmaf(-2.0f, r, 1.0f);
}
__device__ __forceinline__ void prefetch_l2(const void* p) {
    asm volatile("prefetch.global.L2 [%0];" :: "l"(p));
}

__device__ __forceinline__ void red_add_v4(float* p, float a, float b, float c, float d) {
    asm volatile("red.global.add.v4.f32 [%0], {%1,%2,%3,%4};"
                 :: "l"(p), "f"(a), "f"(b), "f"(c), "f"(d) : "memory");
}
__device__ __forceinline__ void red_add_f32(float* p, float a) {
    asm volatile("red.global.add.f32 [%0], %1;" :: "l"(p), "f"(a) : "memory");
}

// ---------------------------------------------------------------------------
// Kernel 1: per-edge message MLP + scatter-add into g_hrxn  (R6 config)
//   msg = tanh([x,s] @ W1m + b1m) @ W2m + b2m      (2->32->16)
// NEW: each thread also L2-prefetches one 128B line of the dxdt kernel's
// 48MB stream data (sto_all/rxn_all/met_all) — HBM is idle during this
// kernel (DRAM=6.8%), L2 is 126MB, so dxdt later hits L2 instead of DRAM.
// ---------------------------------------------------------------------------
#define K1_TPB 128
#define K1_EPT 4
#define LINES_PER_ARRAY (E_ALL * 4 / 128)   // 131072 lines of 128B per 16MB array

__global__ __launch_bounds__(K1_TPB)
void edge_msg_kernel(const float* __restrict__ x_met,
                     const float* __restrict__ sto_sub,
                     const int*   __restrict__ met_sub,
                     const int*   __restrict__ rxn_sub,
                     const float* __restrict__ sto_all,
                     const int*   __restrict__ rxn_all,
                     const int*   __restrict__ met_all) {
    const int tid4 = blockIdx.x * K1_TPB + threadIdx.x;   // quad index
    if (tid4 * K1_EPT >= E_SUB) return;                   // E_SUB % 4 == 0

    // ---- L2 prefetch of dxdt streams: 1 line per thread, 500K threads
    //      cover 3 x 131072 = 393216 lines ----
    {
        int li = tid4;
        if (li < LINES_PER_ARRAY) {
            prefetch_l2(reinterpret_cast<const char*>(sto_all) + (size_t)li * 128);
        } else if (li < 2 * LINES_PER_ARRAY) {
            prefetch_l2(reinterpret_cast<const char*>(rxn_all) + (size_t)(li - LINES_PER_ARRAY) * 128);
        } else if (li < 3 * LINES_PER_ARRAY) {
            prefetch_l2(reinterpret_cast<const char*>(met_all) + (size_t)(li - 2 * LINES_PER_ARRAY) * 128);
        }
    }

    // 3 vector stream loads (LDG.128) + 4 gathers, front-batched
    int4   mi = __ldcs(reinterpret_cast<const int4*>(met_sub) + tid4);
    float4 sv = __ldcs(reinterpret_cast<const float4*>(sto_sub) + tid4);
    int4   ri = __ldcs(reinterpret_cast<const int4*>(rxn_sub) + tid4);

    float x[K1_EPT], s[K1_EPT];
    x[0] = __ldg(x_met + mi.x); x[1] = __ldg(x_met + mi.y);
    x[2] = __ldg(x_met + mi.z); x[3] = __ldg(x_met + mi.w);
    s[0] = sv.x; s[1] = sv.y; s[2] = sv.z; s[3] = sv.w;

    // accumulators init = b2m   (4 edges x 8 u64)
    unsigned long long acc[K1_EPT][MSG_DIM / 2];
    #pragma unroll
    for (int q = 0; q < MSG_DIM / 2; q++) {
        unsigned long long b = pack2(cB2[2 * q], cB2[2 * q + 1]);
        #pragma unroll
        for (int k = 0; k < K1_EPT; k++) acc[k][q] = b;
    }

    #pragma unroll 2
    for (int j = 0; j < HIDDEN; j++) {
        const float wa = cW1[j], wb = cW1[HIDDEN + j], bj = cB1[j];
        float h[K1_EPT];
        #pragma unroll
        for (int k = 0; k < K1_EPT; k++) {
            float u = fmaf(x[k], wa, fmaf(s[k], wb, bj));
            h[k] = tanh_fast(u);
        }
        #pragma unroll
        for (int k = 0; k < K1_EPT; k++) {
            unsigned long long hh = pack2(h[k], h[k]);
            #pragma unroll
            for (int q = 0; q < MSG_DIM / 2; q++)
                acc[k][q] = fma2(hh, cW2p[j * (MSG_DIM / 2) + q], acc[k][q]);
        }
    }

    const int rx[K1_EPT] = {ri.x, ri.y, ri.z, ri.w};
    #pragma unroll
    for (int k = 0; k < K1_EPT; k++) {
        float* p = g_hrxn + (size_t)rx[k] * MSG_DIM;
        #pragma unroll
        for (int q = 0; q < 4; q++) {
            float2 a = unpack2(acc[k][2 * q]);
            float2 b = unpack2(acc[k][2 * q + 1]);
            red_add_v4(p + 4 * q, a.x, a.y, b.x, b.y);
        }
    }
}

// ---------------------------------------------------------------------------
// Kernel 2: per-reaction rate MLP (exact tanh for precision headroom)
// ---------------------------------------------------------------------------
__global__ __launch_bounds__(256)
void rate_kernel(const float* __restrict__ W1r,
                 const float* __restrict__ b1r,
                 const float* __restrict__ W2r,
                 const float* __restrict__ b2r,
                 float* __restrict__ v_out) {
    __shared__ float sW1r[MSG_DIM * HIDDEN];
    __shared__ float sb1r[HIDDEN];
    __shared__ float sW2r[HIDDEN];
    __shared__ float sb2r;

    int t = threadIdx.x;
    for (int i = t; i < MSG_DIM * HIDDEN; i += blockDim.x) sW1r[i] = W1r[i];
    if (t < HIDDEN) { sb1r[t] = b1r[t]; sW2r[t] = W2r[t]; }
    if (t == 0) sb2r = b2r[0];
    __syncthreads();

    int r = blockIdx.x * blockDim.x + t;
    if (r >= N_RXN) return;

    float h[MSG_DIM];
    const float4* hp = reinterpret_cast<const float4*>(g_hrxn + (size_t)r * MSG_DIM);
    #pragma unroll
    for (int q = 0; q < 4; q++) {
        float4 hv = hp[q];
        h[4 * q] = hv.x; h[4 * q + 1] = hv.y; h[4 * q + 2] = hv.z; h[4 * q + 3] = hv.w;
    }

    const float C = 2.8853900817779268f;  // 2*log2(e)
    float y = sb2r;
    #pragma unroll 8
    for (int j = 0; j < HIDDEN; j++) {
        float a = sb1r[j];
        #pragma unroll
        for (int k = 0; k < MSG_DIM; k++) a = fmaf(h[k], sW1r[k * HIDDEN + j], a);
        float z = tanh_from_scaled(a * C);
        y = fmaf(z, sW2r[j], y);
    }
    float sp = fmaxf(y, 0.f) + log1pf(expf(-fabsf(y)));
    v_out[r] = sp;
}

// ---------------------------------------------------------------------------
// Kernel 3: dxdt scatter — R1/R6 winner shape; streams should now be L2-hot
// ---------------------------------------------------------------------------
__global__ __launch_bounds__(256)
void dxdt_kernel(const float* __restrict__ sto_all,
                 const int*   __restrict__ rxn_all,
                 const int*   __restrict__ met_all,
                 const float* __restrict__ v,
                 float* __restrict__ dxdt) {
    int i4 = blockIdx.x * blockDim.x + threadIdx.x;   // one thread = 4 edges
    if (i4 >= E_ALL / 4) return;
    float4 sv = reinterpret_cast<const float4*>(sto_all)[i4];
    int4   rv = reinterpret_cast<const int4*>(rxn_all)[i4];
    int4   mv = reinterpret_cast<const int4*>(met_all)[i4];
    red_add_f32(dxdt + mv.x, sv.x * __ldg(v + rv.x));
    red_add_f32(dxdt + mv.y, sv.y * __ldg(v + rv.y));
    red_add_f32(dxdt + mv.z, sv.z * __ldg(v + rv.z));
    red_add_f32(dxdt + mv.w, sv.w * __ldg(v + rv.w));
}

// ---------------------------------------------------------------------------
// Launch
// ---------------------------------------------------------------------------
extern "C" void kernel_launch(void* const* d_in, const int* in_sizes, int n_in,
                              void* d_out, int out_size) {
    const float* x_met   = (const float*)d_in[0];
    const float* sto_sub = (const float*)d_in[1];
    const float* sto_all = (const float*)d_in[2];
    const float* W1m     = (const float*)d_in[3];
    const float* b1m     = (const float*)d_in[4];
    const float* W2m     = (const float*)d_in[5];
    const float* b2m     = (const float*)d_in[6];
    const float* W1r     = (const float*)d_in[7];
    const float* b1r     = (const float*)d_in[8];
    const float* W2r     = (const float*)d_in[9];
    const float* b2r     = (const float*)d_in[10];
    const int*   met_sub = (const int*)d_in[11];
    const int*   rxn_sub = (const int*)d_in[12];
    const int*   met_all = (const int*)d_in[13];
    const int*   rxn_all = (const int*)d_in[14];

    float* dxdt = (float*)d_out;
    float* v    = (float*)d_out + N_MET;

    // fill constant-memory weights (device-to-device async copies: capturable)
    cudaMemcpyToSymbolAsync(cW2p, W2m, HIDDEN * MSG_DIM * sizeof(float), 0,
                            cudaMemcpyDeviceToDevice);
    cudaMemcpyToSymbolAsync(cW1,  W1m, 2 * HIDDEN * sizeof(float), 0,
                            cudaMemcpyDeviceToDevice);
    cudaMemcpyToSymbolAsync(cB1,  b1m, HIDDEN * sizeof(float), 0,
                            cudaMemcpyDeviceToDevice);
    cudaMemcpyToSymbolAsync(cB2,  b2m, MSG_DIM * sizeof(float), 0,
                            cudaMemcpyDeviceToDevice);

    // zero scratch + dxdt
    void* hrxn_ptr = nullptr;
    cudaGetSymbolAddress(&hrxn_ptr, g_hrxn);
    cudaMemsetAsync(hrxn_ptr, 0, N_RXN * MSG_DIM * sizeof(float));
    cudaMemsetAsync(dxdt, 0, N_MET * sizeof(float));

    int grid1 = (E_SUB / K1_EPT + K1_TPB - 1) / K1_TPB;
    edge_msg_kernel<<<grid1, K1_TPB>>>(x_met, sto_sub, met_sub, rxn_sub,
                                       sto_all, rxn_all, met_all);

    rate_kernel<<<(N_RXN + 255) / 256, 256>>>(W1r, b1r, W2r, b2r, v);

    dxdt_kernel<<<(E_ALL / 4 + 255) / 256, 256>>>(sto_all, rxn_all, met_all, v, dxdt);
}